// round 12
// baseline (speedup 1.0000x reference)
#include <cuda_runtime.h>
#include <cuda_fp16.h>
#include <math.h>

#define B   8
#define C1  256
#define HW1 4096
#define C2  512
#define HW2 1024

#define TPB  256
#define STPB 1024

#define CCH  8                  // channels per tile (== warps per block)
#define HWCH 1024               // hw elements per tile (256 thr * float4)
#define NC1  (C1 / CCH)         // 32
#define NH1  (HW1 / HWCH)       // 4
#define NC2  (C2 / CCH)         // 64
#define NH2  (HW2 / HWCH)       // 1
#define TILES1 (B * NC1 * NH1)  // 1024
#define TILES2 (B * NC2 * NH2)  // 512

#define P2CH 16
#define P2B1 (B * (C1 / P2CH) * (HW1 / HWCH))   // 512
#define P2B2 (B * (C2 / P2CH) * (HW2 / HWCH))   // 256
#define P2TOT (P2B1 + P2B2)                     // 768

#define RGRID 640               // reduce kernel blocks

// ---------------- scratch ----------------------------------------------------
__device__ __align__(128) float g_Gs1p[2][NC1][B * HW1];   // partials (evict_last)
__device__ __align__(128) float g_Gs2p[2][NC2][B * HW2];
__device__ __align__(128) float g_Gc1p[2][B * C1][NH1];
__device__ __align__(128) float g_Gc2p[2][B * C2][NH2];

__device__ __align__(128) float g_Gs1[2][B * HW1];         // compact sums
__device__ __align__(128) float g_Gs2[2][B * HW2];

__device__ __align__(128) __half g_d1[B * C1 * HW1];       // fp16 (s-t) stash (evict_last)
__device__ __align__(128) __half g_d2[B * C2 * HW2];

__device__ __align__(128) float g_Ms1[B * HW1];
__device__ __align__(128) float g_Mc1[B * C1];
__device__ __align__(128) float g_Ms2[B * HW2];
__device__ __align__(128) float g_Mc2[B * C2];

__device__ double g_latpart[16];
__device__ float  g_p2[P2TOT];
__device__ unsigned g_count = 0;

union F2D { float2 f2; double d; };

// ---------------- cache-control helpers --------------------------------------
__device__ __forceinline__ unsigned long long evict_last_policy() {
    unsigned long long pol;
    asm("createpolicy.fractional.L2::evict_last.b64 %0, 1.0;" : "=l"(pol));
    return pol;
}
__device__ __forceinline__ void st_last_u2(void* p, uint2 v, unsigned long long pol) {
    asm volatile("st.global.L2::cache_hint.v2.u32 [%0], {%1,%2}, %3;"
                 :: "l"(p), "r"(v.x), "r"(v.y), "l"(pol) : "memory");
}
__device__ __forceinline__ void st_last_f4(void* p, float4 v, unsigned long long pol) {
    asm volatile("st.global.L2::cache_hint.v4.f32 [%0], {%1,%2,%3,%4}, %5;"
                 :: "l"(p), "f"(v.x), "f"(v.y), "f"(v.z), "f"(v.w), "l"(pol) : "memory");
}
__device__ __forceinline__ void discard_l2(const void* p) {
    unsigned long long g;
    asm("cvta.to.global.u64 %0, %1;" : "=l"(g) : "l"(p));
    asm volatile("discard.global.L2 [%0], 128;" :: "l"(g) : "memory");
}

// ---------------- reduce helpers ---------------------------------------------
__device__ __forceinline__ float blockReduceSum(float v) {
    __shared__ float sh[32];
    int lane = threadIdx.x & 31, warp = threadIdx.x >> 5;
    int nw = blockDim.x >> 5;
#pragma unroll
    for (int o = 16; o > 0; o >>= 1) v += __shfl_down_sync(0xffffffffu, v, o);
    __syncthreads();
    if (lane == 0) sh[warp] = v;
    __syncthreads();
    if (threadIdx.x == 0) {
        float r = 0.f;
        for (int w = 0; w < nw; w++) r += sh[w];
        sh[0] = r;
    }
    __syncthreads();
    return sh[0];
}

__device__ __forceinline__ float blockReduceMax(float v) {
    __shared__ float sh[32];
    int lane = threadIdx.x & 31, warp = threadIdx.x >> 5;
    int nw = blockDim.x >> 5;
#pragma unroll
    for (int o = 16; o > 0; o >>= 1) v = fmaxf(v, __shfl_down_sync(0xffffffffu, v, o));
    __syncthreads();
    if (lane == 0) sh[warp] = v;
    __syncthreads();
    if (threadIdx.x == 0) {
        float r = sh[0];
        for (int w = 1; w < nw; w++) r = fmaxf(r, sh[w]);
        sh[0] = r;
    }
    __syncthreads();
    return sh[0];
}

// ---------------- pass 1: short tiles ----------------------------------------
template <int Cc, int HWc, int NC, int NH>
__device__ __forceinline__ void pass1_tile(
    const float* __restrict__ s, const float* __restrict__ t,
    __half* __restrict__ dst,
    float* __restrict__ Gsp_s, float* __restrict__ Gsp_t,
    float* __restrict__ Gcp_s, float* __restrict__ Gcp_t,
    float2 (*stage)[TPB], int tile)
{
    const int tid = threadIdx.x;
    const int lane = tid & 31, warp = tid >> 5;
    const int b  = tile / (NC * NH);
    const int r  = tile % (NC * NH);
    const int cc = r / NH;
    const int hh = r % NH;
    const int hwbase = hh * HWCH;
    const int c0 = cc * CCH;
    const unsigned long long pol = evict_last_policy();

    const size_t base4 = (((size_t)b * Cc + c0) * HWc + hwbase) / 4;
    const float4* ps = (const float4*)s + base4 + tid;
    const float4* pt = (const float4*)t + base4 + tid;
    uint2* pd = (uint2*)dst + base4 + tid;
    constexpr int STR4 = HWc / 4;

    float4 as = make_float4(0.f, 0.f, 0.f, 0.f);
    float4 at = make_float4(0.f, 0.f, 0.f, 0.f);

#pragma unroll
    for (int ci = 0; ci < CCH; ci++) {
        float4 vs = __ldcs(&ps[(size_t)ci * STR4]);   // evict-first stream
        float4 vt = __ldcs(&pt[(size_t)ci * STR4]);

        __half2 h01 = __floats2half2_rn(vs.x - vt.x, vs.y - vt.y);
        __half2 h23 = __floats2half2_rn(vs.z - vt.z, vs.w - vt.w);
        uint2 u;
        u.x = *reinterpret_cast<const unsigned*>(&h01);
        u.y = *reinterpret_cast<const unsigned*>(&h23);
        st_last_u2(&pd[(size_t)ci * STR4], u, pol);   // stash pinned in L2

        vs.x = fabsf(vs.x); vs.y = fabsf(vs.y); vs.z = fabsf(vs.z); vs.w = fabsf(vs.w);
        vt.x = fabsf(vt.x); vt.y = fabsf(vt.y); vt.z = fabsf(vt.z); vt.w = fabsf(vt.w);
        as.x += vs.x; as.y += vs.y; as.z += vs.z; as.w += vs.w;
        at.x += vt.x; at.y += vt.y; at.z += vt.z; at.w += vt.w;

        stage[ci][tid] = make_float2((vs.x + vs.y) + (vs.z + vs.w),
                                     (vt.x + vt.y) + (vt.z + vt.w));
    }

    // spatial partials pinned in L2 too
    st_last_f4(((float4*)(Gsp_s + (size_t)cc * (B * HWc) + b * HWc + hwbase)) + tid, as, pol);
    st_last_f4(((float4*)(Gsp_t + (size_t)cc * (B * HWc) + b * HWc + hwbase)) + tid, at, pol);

    __syncthreads();

    float2 acc = make_float2(0.f, 0.f);
#pragma unroll
    for (int k = 0; k < TPB / 32; k++) {
        float2 v = stage[warp][lane + 32 * k];
        acc.x += v.x; acc.y += v.y;
    }
    F2D u2; u2.f2 = acc;
#pragma unroll
    for (int o = 16; o > 0; o >>= 1) {
        F2D v; v.d = __shfl_down_sync(0xffffffffu, u2.d, o);
        u2.f2.x += v.f2.x; u2.f2.y += v.f2.y;
    }
    if (lane == 0) {
        int idx = (b * Cc + c0 + warp) * NH + hh;
        Gcp_s[idx] = u2.f2.x;
        Gcp_t[idx] = u2.f2.y;
    }
}

__global__ void __launch_bounds__(TPB, 6)
pass1_kernel(const float* __restrict__ s1, const float* __restrict__ t1,
             const float* __restrict__ s2, const float* __restrict__ t2) {
    __shared__ float2 stage[CCH][TPB];   // 16 KB
    int bid = blockIdx.x;
    if (bid < TILES1)
        pass1_tile<C1, HW1, NC1, NH1>(s1, t1, g_d1,
            &g_Gs1p[0][0][0], &g_Gs1p[1][0][0],
            &g_Gc1p[0][0][0], &g_Gc1p[1][0][0], stage, bid);
    else
        pass1_tile<C2, HW2, NC2, NH2>(s2, t2, g_d2,
            &g_Gs2p[0][0][0], &g_Gs2p[1][0][0],
            &g_Gc2p[0][0][0], &g_Gc2p[1][0][0], stage, bid - TILES1);
}

// ---------------- reduce: Gs partials -> compact, then discard ----------------
__global__ void reduce_kernel() {
    const unsigned NT = (unsigned)gridDim.x * TPB;
    const unsigned gt = blockIdx.x * TPB + threadIdx.x;

    for (unsigned i = gt; i < B * HW1; i += NT) {
        float ss = 0.f, st = 0.f;
#pragma unroll
        for (int p = 0; p < NC1; p++) { ss += g_Gs1p[0][p][i]; st += g_Gs1p[1][p][i]; }
        g_Gs1[0][i] = ss; g_Gs1[1][i] = st;
    }
    for (unsigned i = gt; i < B * HW2; i += NT) {
        float ss = 0.f, st = 0.f;
#pragma unroll
        for (int p = 0; p < NC2; p++) { ss += g_Gs2p[0][p][i]; st += g_Gs2p[1][p][i]; }
        g_Gs2[0][i] = ss; g_Gs2[1][i] = st;
    }
    __syncthreads();   // this block's reads complete before its discards

    // discard this block's own 128B lines (32 floats) across all partials
    for (unsigned i0 = blockIdx.x * TPB; i0 < B * HW1; i0 += NT) {
        unsigned li = i0 + threadIdx.x;
        if ((li & 31) == 0) {
#pragma unroll
            for (int p = 0; p < NC1; p++) {
                discard_l2(&g_Gs1p[0][p][li]);
                discard_l2(&g_Gs1p[1][p][li]);
            }
        }
    }
    for (unsigned i0 = blockIdx.x * TPB; i0 < B * HW2; i0 += NT) {
        unsigned li = i0 + threadIdx.x;
        if ((li & 31) == 0) {
#pragma unroll
            for (int p = 0; p < NC2; p++) {
                discard_l2(&g_Gs2p[0][p][li]);
                discard_l2(&g_Gs2p[1][p][li]);
            }
        }
    }
}

// ---------------- softmax + lat (16 blocks; compact Gs) ----------------------
template <int Cc, int HWc, int NPART>
__device__ __forceinline__ void softmax_level(
    const float* __restrict__ Gs_s, const float* __restrict__ Gs_t,
    const float* __restrict__ Gcp_s, const float* __restrict__ Gcp_t,
    float* __restrict__ Ms, float* __restrict__ Mc,
    int b, float* zbuf, double* latout)
{
    const int tid = threadIdx.x;

    float latp = 0.f, mx = -INFINITY;
    for (int i = tid; i < HWc; i += STPB) {
        float ss = Gs_s[b * HWc + i];
        float st = Gs_t[b * HWc + i];
        float d = ss - st;
        latp += d * d;
        float z = (ss + st) * (2.0f / (float)Cc);   // /C then /T (T=0.5)
        zbuf[i] = z;
        mx = fmaxf(mx, z);
    }
    float m = blockReduceMax(mx);
    float se = 0.f;
    for (int i = tid; i < HWc; i += STPB) {
        float e = __expf(zbuf[i] - m);
        zbuf[i] = e;
        se += e;
    }
    float S = blockReduceSum(se);
    float sc = (float)HWc / S;
    for (int i = tid; i < HWc; i += STPB) Ms[b * HWc + i] = zbuf[i] * sc;
    float lat_s = blockReduceSum(latp);

    float latc = 0.f, mxc = -INFINITY;
    for (int i = tid; i < Cc; i += STPB) {
        float cs = 0.f, ct = 0.f;
#pragma unroll
        for (int k = 0; k < NPART; k++) {
            cs += Gcp_s[(size_t)(b * Cc + i) * NPART + k];
            ct += Gcp_t[(size_t)(b * Cc + i) * NPART + k];
        }
        float d = cs - ct;
        latc += d * d;
        float z = (cs + ct) * (2.0f / (float)HWc);
        zbuf[i] = z;
        mxc = fmaxf(mxc, z);
    }
    float m2 = blockReduceMax(mxc);
    float sec = 0.f;
    for (int i = tid; i < Cc; i += STPB) {
        float e = __expf(zbuf[i] - m2);
        zbuf[i] = e;
        sec += e;
    }
    float Sc = blockReduceSum(sec);
    float scc = (float)Cc / Sc;
    for (int i = tid; i < Cc; i += STPB) Mc[b * Cc + i] = zbuf[i] * scc;
    float lat_c = blockReduceSum(latc);

    if (tid == 0)
        *latout = (double)lat_s / ((double)Cc * (double)Cc) +
                  (double)lat_c / ((double)HWc * (double)HWc);
}

__global__ void softmax_kernel() {
    __shared__ float zbuf[HW1];   // 16 KB
    int bid = blockIdx.x;
    if (bid == 0 && threadIdx.x == 0) g_count = 0;   // reset last-block counter
    if (bid < B)
        softmax_level<C1, HW1, NH1>(g_Gs1[0], g_Gs1[1],
            &g_Gc1p[0][0][0], &g_Gc1p[1][0][0],
            g_Ms1, g_Mc1, bid, zbuf, &g_latpart[bid]);
    else
        softmax_level<C2, HW2, NH2>(g_Gs2[0], g_Gs2[1],
            &g_Gc2p[0][0][0], &g_Gc2p[1][0][0],
            g_Ms2, g_Mc2, bid - B, zbuf, &g_latpart[bid]);
}

// ---------------- pass 2: L2-resident stash read, fused final -----------------
template <int Cc, int HWc>
__device__ __forceinline__ float pass2_block(
    const __half* __restrict__ dsrc,
    const float* __restrict__ Ms, const float* __restrict__ Mc,
    int b, int c0, int hwbase)
{
    const int tid = threadIdx.x;
    float4 ms = *(const float4*)(Ms + (size_t)b * HWc + hwbase + tid * 4);

    float acc = 0.f;
#pragma unroll
    for (int ci = 0; ci < P2CH; ci++) {
        const int c = c0 + ci;
        const uint2* p = (const uint2*)dsrc +
                         (((size_t)b * Cc + c) * HWc + hwbase) / 4 + tid;
        uint2 v = *p;
        float2 f0 = __half22float2(*reinterpret_cast<const __half2*>(&v.x));
        float2 f1 = __half22float2(*reinterpret_cast<const __half2*>(&v.y));
        float e = f0.x * f0.x * ms.x + f0.y * f0.y * ms.y
                + f1.x * f1.x * ms.z + f1.y * f1.y * ms.w;
        acc += e * Mc[b * Cc + c];
    }
    return acc;
}

template <int Cc, int HWc>
__device__ __forceinline__ void pass2_discard_block(
    const __half* dsrc, int b, int c0, int hwbase)
{
    const int ci = threadIdx.x >> 4;
    const int ln = threadIdx.x & 15;
    const __half* p = dsrc + ((size_t)b * Cc + c0 + ci) * HWc + hwbase + ln * 64;
    discard_l2(p);
}

__global__ void __launch_bounds__(TPB, 6)
pass2_kernel(float* out, int out_size) {
    int bid = blockIdx.x;
    float acc;
    int b, c0, hwbase;
    if (bid < P2B1) {
        b = bid / ((C1 / P2CH) * (HW1 / HWCH));
        int r = bid % ((C1 / P2CH) * (HW1 / HWCH));
        c0 = (r / (HW1 / HWCH)) * P2CH;
        hwbase = (r % (HW1 / HWCH)) * HWCH;
        acc = pass2_block<C1, HW1>(g_d1, g_Ms1, g_Mc1, b, c0, hwbase);
    } else {
        int id = bid - P2B1;
        b = id / (C2 / P2CH);
        c0 = (id % (C2 / P2CH)) * P2CH;
        hwbase = 0;
        acc = pass2_block<C2, HW2>(g_d2, g_Ms2, g_Mc2, b, c0, hwbase);
    }
    float bl = blockReduceSum(acc);   // barrier: block's stash reads complete

    if (bid < P2B1) pass2_discard_block<C1, HW1>(g_d1, b, c0, hwbase);
    else            pass2_discard_block<C2, HW2>(g_d2, b, c0, hwbase);

    __shared__ bool isLast;
    if (threadIdx.x == 0) {
        g_p2[bid] = bl;
        __threadfence();
        unsigned old = atomicAdd(&g_count, 1u);
        isLast = (old == P2TOT - 1);
    }
    __syncthreads();
    if (!isLast) return;

    __threadfence();
    int tid = threadIdx.x;
    double a1 = 0.0, a2 = 0.0;
    for (int i = tid; i < P2B1; i += TPB) a1 += (double)g_p2[i];
    for (int i = P2B1 + tid; i < P2TOT; i += TPB) a2 += (double)g_p2[i];

    __shared__ double sh1[32], sh2[32];
    int lane = tid & 31, warp = tid >> 5;
#pragma unroll
    for (int o = 16; o > 0; o >>= 1) {
        a1 += __shfl_down_sync(0xffffffffu, a1, o);
        a2 += __shfl_down_sync(0xffffffffu, a2, o);
    }
    if (lane == 0) { sh1[warp] = a1; sh2[warp] = a2; }
    __syncthreads();
    if (tid == 0) {
        double s1 = 0.0, s2 = 0.0;
        for (int w = 0; w < TPB / 32; w++) { s1 += sh1[w]; s2 += sh2[w]; }
        double lat = 0.0;
        for (int i = 0; i < 16; i++) lat += g_latpart[i];
        double lam = sqrt(s1) + sqrt(s2);
        double att = (4e-4 * lat + 2e-2 * lam) / (double)B / 2.0;   // ATT=1
        out[0] = (float)(att * (double)B);
        if (out_size > 1) out[1] = (float)att;
    }
}

// ---------------- launch ------------------------------------------------------
extern "C" void kernel_launch(void* const* d_in, const int* in_sizes, int n_in,
                              void* d_out, int out_size) {
    const float* stu1 = (const float*)d_in[1];
    const float* tea1 = (const float*)d_in[2];
    const float* stu2 = (const float*)d_in[3];
    const float* tea2 = (const float*)d_in[4];
    float* out = (float*)d_out;

    pass1_kernel<<<TILES1 + TILES2, TPB>>>(stu1, tea1, stu2, tea2);
    reduce_kernel<<<RGRID, TPB>>>();
    softmax_kernel<<<16, STPB>>>();
    pass2_kernel<<<P2TOT, TPB>>>(out, out_size);
}